// round 1
// baseline (speedup 1.0000x reference)
#include <cuda_runtime.h>

// Problem constants
#define BB 8
#define CC 64
#define FF 3
#define HH 192
#define WW 192
#define HO 182
#define WO 182
#define C1S 0.01f   // (0.01*10)^2
#define C2S 0.09f   // (0.03*10)^2
#define INV_NPIX (1.0f/33124.0f)  // 1/(182*182)

// Scratch: mu_f/sig_f per (b,f) plane, packed as float2 {mu, sig}
__device__ float2 g_musig[BB * FF * HO * WO];
// Scratch: ssim_info [B,F,C]
__device__ float g_ssim[BB * FF * CC];

// 11-tap gaussian weights (sigma=1.5), compile-time constants -> FFMA-imm
__device__ __forceinline__ float wt(int i) {
    switch (i) {
        case 0: case 10: return 0.00102838f;
        case 1: case 9:  return 0.00759876f;
        case 2: case 8:  return 0.03600077f;
        case 3: case 7:  return 0.10936069f;
        case 4: case 6:  return 0.21300553f;
        default:         return 0.26601173f;  // center
    }
}

// Transposed-FIR push: feeds one new sample h, returns completed output
// (valid once 11 samples have been pushed). 10-register state per FIR.
__device__ __forceinline__ float fir_push(float (&P)[10], float h) {
    float out = fmaf(wt(10), h, P[0]);
#pragma unroll
    for (int m = 0; m < 9; m++) P[m] = fmaf(wt(9 - m), h, P[m + 1]);
    P[9] = wt(0) * h;
    return out;
}

// ---------------------------------------------------------------------------
// K1: per-(b,f) mu_f / sig_f planes. grid (24, 4 bands), 192 threads.
// ---------------------------------------------------------------------------
__global__ void __launch_bounds__(192) k1_musig(const float* __restrict__ xf) {
    const int bf = blockIdx.x;          // b*3 + f
    const int band = blockIdx.y;        // 0..3
    const int t = threadIdx.x;          // 0..191

    __shared__ float fs[WW];
    __shared__ float vf[WW], vff[WW];

    const int bs[5] = {0, 46, 92, 137, 182};
    const int r0 = bs[band], r1 = bs[band + 1];

    const float* plane = xf + (size_t)bf * HH * WW;

    float Pf[10], Pff[10];
#pragma unroll
    for (int m = 0; m < 10; m++) { Pf[m] = 0.f; Pff[m] = 0.f; }

    // prime stage with first row of this band
    float4 pref;
    if (t < 48) {
        pref = *reinterpret_cast<const float4*>(plane + (size_t)r0 * WW + 4 * t);
        reinterpret_cast<float4*>(fs)[t] = pref;
    }
    __syncthreads();

    const int rend = r1 + 10;
    for (int r = r0; r < rend; ++r) {
        // prefetch next row
        if (t < 48 && r + 1 < rend) {
            pref = *reinterpret_cast<const float4*>(plane + (size_t)(r + 1) * WW + 4 * t);
        }
        // vertical FIR (all 192 columns)
        float h = fs[t];
        float of  = fir_push(Pf, h);
        float off = fir_push(Pff, h * h);
        const int ro = r - 10;
        if (ro >= r0) { vf[t] = of; vff[t] = off; }
        __syncthreads();

        // horizontal 11-tap + finalize, 2 cols/thread
        if (ro >= r0 && t < 91) {
            const int j0 = 2 * t;
            float a[12], b[12];
#pragma unroll
            for (int i = 0; i < 6; i++) {
                float2 u = *reinterpret_cast<const float2*>(&vf[j0 + 2 * i]);
                float2 v = *reinterpret_cast<const float2*>(&vff[j0 + 2 * i]);
                a[2 * i] = u.x; a[2 * i + 1] = u.y;
                b[2 * i] = v.x; b[2 * i + 1] = v.y;
            }
            float mu0 = 0.f, mu1 = 0.f, s0 = 0.f, s1 = 0.f;
#pragma unroll
            for (int i = 0; i < 11; i++) {
                mu0 = fmaf(wt(i), a[i], mu0);
                mu1 = fmaf(wt(i), a[i + 1], mu1);
                s0  = fmaf(wt(i), b[i], s0);
                s1  = fmaf(wt(i), b[i + 1], s1);
            }
            s0 = s0 - mu0 * mu0;
            s1 = s1 - mu1 * mu1;
            float4 st = make_float4(mu0, s0, mu1, s1);
            *reinterpret_cast<float4*>(&g_musig[((size_t)bf * HO + ro) * WO + j0]) = st;
        }
        if (t < 48 && r + 1 < rend) reinterpret_cast<float4*>(fs)[t] = pref;
        __syncthreads();
    }
}

// ---------------------------------------------------------------------------
// K2: main SSIM kernel. grid (c=64, b=8), 192 threads. One CTA per (b,c).
// Vertical register FIR (5 quantities) -> SMEM row -> horizontal + SSIM.
// ---------------------------------------------------------------------------
__global__ void __launch_bounds__(192) k2_ssim(const float* __restrict__ x,
                                               const float* __restrict__ xf) {
    const int c = blockIdx.x;
    const int b = blockIdx.y;
    const int t = threadIdx.x;

    __shared__ float xs[WW], f0s[WW], f1s[WW], f2s[WW];
    __shared__ float vs[5][WW];
    __shared__ float red[3][96];

    const float* xp = x + ((size_t)(b * CC + c)) * HH * WW;
    const float* fp = xf + (size_t)b * FF * HH * WW;

    // stage-load mapping: 4 groups of 48 threads, one row of 192 floats each
    const int g = t / 48, k = t % 48;
    const float* srcbase = (g == 0) ? xp : fp + (size_t)(g - 1) * HH * WW;
    float* dst = (g == 0) ? xs : (g == 1) ? f0s : (g == 2) ? f1s : f2s;

    float P[5][10];
#pragma unroll
    for (int q = 0; q < 5; q++)
#pragma unroll
        for (int m = 0; m < 10; m++) P[q][m] = 0.f;

    float acc0 = 0.f, acc1 = 0.f, acc2 = 0.f;

    // prime row 0
    float4 pref = *reinterpret_cast<const float4*>(srcbase + 4 * k);
    reinterpret_cast<float4*>(dst)[k] = pref;
    __syncthreads();

    for (int r = 0; r < HH; ++r) {
        if (r + 1 < HH) {
            pref = *reinterpret_cast<const float4*>(srcbase + (size_t)(r + 1) * WW + 4 * k);
        }
        // ---- vertical FIRs ----
        float xv = xs[t];
        float f0v = f0s[t], f1v = f1s[t], f2v = f2s[t];
        float o0 = fir_push(P[0], xv);
        float o1 = fir_push(P[1], xv * xv);
        float o2 = fir_push(P[2], f0v * xv);
        float o3 = fir_push(P[3], f1v * xv);
        float o4 = fir_push(P[4], f2v * xv);
        const int ro = r - 10;
        if (ro >= 0) {
            vs[0][t] = o0; vs[1][t] = o1; vs[2][t] = o2; vs[3][t] = o3; vs[4][t] = o4;
        }
        __syncthreads();

        // ---- horizontal + SSIM, 2 cols/thread ----
        if (ro >= 0 && t < 91) {
            const int j0 = 2 * t;
            float Hq[5][2];
#pragma unroll
            for (int q = 0; q < 5; q++) {
                float v[12];
#pragma unroll
                for (int i = 0; i < 6; i++) {
                    float2 u = *reinterpret_cast<const float2*>(&vs[q][j0 + 2 * i]);
                    v[2 * i] = u.x; v[2 * i + 1] = u.y;
                }
                float s0 = 0.f, s1 = 0.f;
#pragma unroll
                for (int i = 0; i < 11; i++) {
                    s0 = fmaf(wt(i), v[i], s0);
                    s1 = fmaf(wt(i), v[i + 1], s1);
                }
                Hq[q][0] = s0; Hq[q][1] = s1;
            }
            // mu_f/sig_f for both cols, all 3 f: 3x LDG.128
            float4 mf[3];
#pragma unroll
            for (int f = 0; f < 3; f++) {
                mf[f] = *reinterpret_cast<const float4*>(
                    &g_musig[((size_t)(b * FF + f) * HO + ro) * WO + j0]);
            }
#pragma unroll
            for (int col = 0; col < 2; col++) {
                float mux = Hq[0][col];
                float sigx = Hq[1][col] - mux * mux;
                float mx2c = fmaf(mux, mux, C1S);
                float sxc = sigx + C2S;
#pragma unroll
                for (int f = 0; f < 3; f++) {
                    float muf  = col ? mf[f].z : mf[f].x;
                    float sigf = col ? mf[f].w : mf[f].y;
                    float tp  = muf * mux;
                    float sfx = Hq[2 + f][col] - tp;
                    float v1  = fmaf(2.f, sfx, C2S);
                    float v2  = sigf + sxc;
                    float num = fmaf(2.f, tp, C1S) * v1;
                    float den = fmaf(muf, muf, mx2c) * v2;
                    float rr  = __fdividef(num, den);
                    if (f == 0) acc0 += rr; else if (f == 1) acc1 += rr; else acc2 += rr;
                }
            }
        }
        if (r + 1 < HH) reinterpret_cast<float4*>(dst)[k] = pref;
        __syncthreads();
    }

    // ---- block reduce acc over the 91 active threads ----
    if (t < 91) { red[0][t] = acc0; red[1][t] = acc1; red[2][t] = acc2; }
    else if (t < 96) { red[0][t] = 0.f; red[1][t] = 0.f; red[2][t] = 0.f; }
    __syncthreads();
    if (t < 3) {
        float s = 0.f;
        for (int i = 0; i < 96; i++) s += red[t][i];
        g_ssim[(size_t)(b * FF + t) * CC + c] = s * INV_NPIX;
    }
}

// ---------------------------------------------------------------------------
// K3: spatial gate conv + MLP + sigmoid + output assembly. 1 block, 512 thr.
// ---------------------------------------------------------------------------
__global__ void __launch_bounds__(512) k3_gate(const float* __restrict__ sw,
                                               const float* __restrict__ W1,
                                               const float* __restrict__ b1,
                                               const float* __restrict__ W2,
                                               const float* __restrict__ b2,
                                               float* __restrict__ out,
                                               int out_size) {
    __shared__ float si[BB][FF][CC];
    __shared__ float gg[BB][CC];
    __shared__ float h1[BB][CC];

    const int t = threadIdx.x;
    const int b = t >> 6, c = t & 63;

    for (int i = t; i < BB * FF * CC; i += 512) (&si[0][0][0])[i] = g_ssim[i];
    __syncthreads();

    // conv (3,1) over C with padding 1, in-channels F, out-channel 1 + relu
    float s = 0.f;
#pragma unroll
    for (int f = 0; f < 3; f++) {
#pragma unroll
        for (int kk = 0; kk < 3; kk++) {
            int cc = c + kk - 1;
            if (cc >= 0 && cc < CC) s = fmaf(sw[f * 3 + kk], si[b][f][cc], s);
        }
    }
    gg[b][c] = fmaxf(s, 0.f);
    __syncthreads();

    float a = b1[c];
#pragma unroll 8
    for (int j = 0; j < CC; j++) a = fmaf(gg[b][j], W1[c * CC + j], a);
    h1[b][c] = fmaxf(a, 0.f);
    __syncthreads();

    float o = b2[c];
#pragma unroll 8
    for (int j = 0; j < CC; j++) o = fmaf(h1[b][j], W2[c * CC + j], o);
    out[b * CC + c] = 1.f / (1.f + expf(-o));

    // second output: ssim_info [B,F,C] appended after the sigmoid [B,C]
    if (out_size >= BB * CC + BB * FF * CC) {
        for (int i = t; i < BB * FF * CC; i += 512) out[BB * CC + i] = g_ssim[i];
    }
}

// ---------------------------------------------------------------------------
extern "C" void kernel_launch(void* const* d_in, const int* in_sizes, int n_in,
                              void* d_out, int out_size) {
    const float* x  = (const float*)d_in[0];
    const float* xf = (const float*)d_in[1];
    const float* sw = (const float*)d_in[2];
    const float* W1 = (const float*)d_in[3];
    const float* b1 = (const float*)d_in[4];
    const float* W2 = (const float*)d_in[5];
    const float* b2 = (const float*)d_in[6];
    float* out = (float*)d_out;

    k1_musig<<<dim3(BB * FF, 4), 192>>>(xf);
    k2_ssim<<<dim3(CC, BB), 192>>>(x, xf);
    k3_gate<<<1, 512>>>(sw, W1, b1, W2, b2, out, out_size);
}

// round 2
// speedup vs baseline: 1.7870x; 1.7870x over previous
#include <cuda_runtime.h>

// Problem constants
#define BB 8
#define CC 64
#define FF 3
#define HH 192
#define WW 192
#define HO 182
#define WO 182
#define C1S 0.01f   // (0.01*10)^2
#define C2S 0.09f   // (0.03*10)^2
#define INV_NPIX (1.0f/33124.0f)  // 1/(182*182)
#define NBAND 4

// Scratch: mu_f/sig_f per (b,f) plane, packed as float2 {mu, sig}
__device__ float2 g_musig[BB * FF * HO * WO];
// Scratch: per-band partial ssim sums [band][B][F][C]
__device__ float g_part[NBAND * BB * FF * CC];

// 11-tap gaussian weights (sigma=1.5), compile-time constants -> FFMA-imm
__device__ __forceinline__ float wt(int i) {
    switch (i) {
        case 0: case 10: return 0.00102838f;
        case 1: case 9:  return 0.00759876f;
        case 2: case 8:  return 0.03600077f;
        case 3: case 7:  return 0.10936069f;
        case 4: case 6:  return 0.21300553f;
        default:         return 0.26601173f;  // center
    }
}

// Transposed-FIR push: feeds one new sample h, returns completed output
// (valid once 11 samples have been pushed). 10-register state per FIR.
__device__ __forceinline__ float fir_push(float (&P)[10], float h) {
    float out = fmaf(wt(10), h, P[0]);
#pragma unroll
    for (int m = 0; m < 9; m++) P[m] = fmaf(wt(9 - m), h, P[m + 1]);
    P[9] = wt(0) * h;
    return out;
}

// ---------------------------------------------------------------------------
// K1: per-(b,f) mu_f / sig_f planes. grid (24, 8 bands), 192 threads.
// ---------------------------------------------------------------------------
__global__ void __launch_bounds__(192) k1_musig(const float* __restrict__ xf) {
    const int bf = blockIdx.x;          // b*3 + f
    const int band = blockIdx.y;        // 0..7
    const int t = threadIdx.x;          // 0..191

    __shared__ float fs[WW];
    __shared__ float vf[WW], vff[WW];

    const int bs[9] = {0, 23, 46, 69, 92, 115, 138, 161, 182};
    const int r0 = bs[band], r1 = bs[band + 1];

    const float* plane = xf + (size_t)bf * HH * WW;

    float Pf[10], Pff[10];
#pragma unroll
    for (int m = 0; m < 10; m++) { Pf[m] = 0.f; Pff[m] = 0.f; }

    float4 pref;
    if (t < 48) {
        pref = *reinterpret_cast<const float4*>(plane + (size_t)r0 * WW + 4 * t);
        reinterpret_cast<float4*>(fs)[t] = pref;
    }
    __syncthreads();

    const int rend = r1 + 10;
    for (int r = r0; r < rend; ++r) {
        if (t < 48 && r + 1 < rend) {
            pref = *reinterpret_cast<const float4*>(plane + (size_t)(r + 1) * WW + 4 * t);
        }
        float h = fs[t];
        float of  = fir_push(Pf, h);
        float off = fir_push(Pff, h * h);
        const int ro = r - 10;
        if (ro >= r0) { vf[t] = of; vff[t] = off; }
        __syncthreads();

        if (ro >= r0 && t < 91) {
            const int j0 = 2 * t;
            float a[12], b[12];
#pragma unroll
            for (int i = 0; i < 6; i++) {
                float2 u = *reinterpret_cast<const float2*>(&vf[j0 + 2 * i]);
                float2 v = *reinterpret_cast<const float2*>(&vff[j0 + 2 * i]);
                a[2 * i] = u.x; a[2 * i + 1] = u.y;
                b[2 * i] = v.x; b[2 * i + 1] = v.y;
            }
            float mu0 = 0.f, mu1 = 0.f, s0 = 0.f, s1 = 0.f;
#pragma unroll
            for (int i = 0; i < 11; i++) {
                mu0 = fmaf(wt(i), a[i], mu0);
                mu1 = fmaf(wt(i), a[i + 1], mu1);
                s0  = fmaf(wt(i), b[i], s0);
                s1  = fmaf(wt(i), b[i + 1], s1);
            }
            s0 = s0 - mu0 * mu0;
            s1 = s1 - mu1 * mu1;
            float4 st = make_float4(mu0, s0, mu1, s1);
            *reinterpret_cast<float4*>(&g_musig[((size_t)bf * HO + ro) * WO + j0]) = st;
        }
        if (t < 48 && r + 1 < rend) reinterpret_cast<float4*>(fs)[t] = pref;
        __syncthreads();
    }
}

// ---------------------------------------------------------------------------
// K2: main SSIM kernel. grid (c=64, b=8, band=4), 192 threads.
// 2 input rows per iteration, double-buffered stage + vertical outputs,
// ONE __syncthreads per iteration. Horizontal phase uses 182/192 threads.
// ---------------------------------------------------------------------------
struct VSBuf { float v[2][5][WW]; };   // [rowoff][quantity][col]

__device__ __forceinline__ void do_horiz(const VSBuf& vs, int roBase,
                                         int o0, int o1, int b, int t,
                                         float& acc0, float& acc1, float& acc2) {
    if (t >= 182) return;
    const int rr = (t >= 91) ? 1 : 0;
    const int jp = t - (rr ? 91 : 0);
    const int ro = roBase + rr;
    if (ro < o0 || ro >= o1) return;
    const int j0 = 2 * jp;

    float Hq[5][2];
#pragma unroll
    for (int q = 0; q < 5; q++) {
        float v[12];
#pragma unroll
        for (int i = 0; i < 6; i++) {
            float2 u = *reinterpret_cast<const float2*>(&vs.v[rr][q][j0 + 2 * i]);
            v[2 * i] = u.x; v[2 * i + 1] = u.y;
        }
        float s0 = 0.f, s1 = 0.f;
#pragma unroll
        for (int i = 0; i < 11; i++) {
            s0 = fmaf(wt(i), v[i], s0);
            s1 = fmaf(wt(i), v[i + 1], s1);
        }
        Hq[q][0] = s0; Hq[q][1] = s1;
    }
    float4 mf[3];
#pragma unroll
    for (int f = 0; f < 3; f++) {
        mf[f] = *reinterpret_cast<const float4*>(
            &g_musig[((size_t)(b * FF + f) * HO + ro) * WO + j0]);
    }
#pragma unroll
    for (int col = 0; col < 2; col++) {
        float mux = Hq[0][col];
        float sigx = Hq[1][col] - mux * mux;
        float mx2c = fmaf(mux, mux, C1S);
        float sxc = sigx + C2S;
#pragma unroll
        for (int f = 0; f < 3; f++) {
            float muf  = col ? mf[f].z : mf[f].x;
            float sigf = col ? mf[f].w : mf[f].y;
            float tp  = muf * mux;
            float sfx = Hq[2 + f][col] - tp;
            float v1  = fmaf(2.f, sfx, C2S);
            float v2  = sigf + sxc;
            float num = fmaf(2.f, tp, C1S) * v1;
            float den = fmaf(muf, muf, mx2c) * v2;
            float rr2 = __fdividef(num, den);
            if (f == 0) acc0 += rr2; else if (f == 1) acc1 += rr2; else acc2 += rr2;
        }
    }
}

__global__ void __launch_bounds__(192) k2_ssim(const float* __restrict__ x,
                                               const float* __restrict__ xf) {
    const int c = blockIdx.x;
    const int b = blockIdx.y;
    const int band = blockIdx.z;
    const int t = threadIdx.x;

    __shared__ float stage[2][2][4][WW];  // [buf][rowoff][plane][col]
    __shared__ VSBuf vsb[2];
    __shared__ float red[3][192];

    const int obs[5] = {0, 46, 92, 138, 182};
    const int o0 = obs[band], o1 = obs[band + 1];
    const int rin0 = o0;
    const int rinEnd = o1 + 10;
    const int nIter = (rinEnd - rin0) >> 1;

    const float* xp = x + ((size_t)(b * CC + c)) * HH * WW;
    const float* fp = xf + (size_t)b * FF * HH * WW;

    // Stage loader mapping: thread t loads 2 float4 chunks:
    //   plane p0 = t/96 (0->x, 1->f0), and plane p0+2 (f1 or f2)
    //   rowoff = (t/48)&1, chunk idx k = t%48
    const int p0 = t / 96;
    const int ro_ld = (t / 48) & 1;
    const int kk = t % 48;
    const float* srcA = p0 ? fp : xp;
    const float* srcB = fp + (size_t)(p0 + 1) * HH * WW;

    float P[5][10];
#pragma unroll
    for (int q = 0; q < 5; q++)
#pragma unroll
        for (int m = 0; m < 10; m++) P[q][m] = 0.f;

    float acc0 = 0.f, acc1 = 0.f, acc2 = 0.f;

    // prime: load rows rin0, rin0+1 into stage[0]
    {
        const int r = rin0 + ro_ld;
        float4 a = *reinterpret_cast<const float4*>(srcA + (size_t)r * WW + 4 * kk);
        float4 bq = *reinterpret_cast<const float4*>(srcB + (size_t)r * WW + 4 * kk);
        reinterpret_cast<float4*>(&stage[0][ro_ld][p0][0])[kk] = a;
        reinterpret_cast<float4*>(&stage[0][ro_ld][p0 + 2][0])[kk] = bq;
    }
    __syncthreads();

    for (int i = 0; i < nIter; ++i) {
        const int buf = i & 1;
        // prefetch next 2 rows
        float4 pa, pb;
        const bool pfv = (i + 1 < nIter);
        if (pfv) {
            const int r = rin0 + 2 * (i + 1) + ro_ld;
            pa = *reinterpret_cast<const float4*>(srcA + (size_t)r * WW + 4 * kk);
            pb = *reinterpret_cast<const float4*>(srcB + (size_t)r * WW + 4 * kk);
        }
        // ---- vertical FIRs (2 rows) ----
#pragma unroll
        for (int rw = 0; rw < 2; rw++) {
            float xv  = stage[buf][rw][0][t];
            float f0v = stage[buf][rw][1][t];
            float f1v = stage[buf][rw][2][t];
            float f2v = stage[buf][rw][3][t];
            vsb[buf].v[rw][0][t] = fir_push(P[0], xv);
            vsb[buf].v[rw][1][t] = fir_push(P[1], xv * xv);
            vsb[buf].v[rw][2][t] = fir_push(P[2], f0v * xv);
            vsb[buf].v[rw][3][t] = fir_push(P[3], f1v * xv);
            vsb[buf].v[rw][4][t] = fir_push(P[4], f2v * xv);
        }
        // ---- horizontal + SSIM for previous iteration's vertical output ----
        if (i > 0) {
            const int roBase = rin0 + 2 * (i - 1) - 10;
            do_horiz(vsb[buf ^ 1], roBase, o0, o1, b, t, acc0, acc1, acc2);
        }
        // commit prefetch
        if (pfv) {
            reinterpret_cast<float4*>(&stage[buf ^ 1][ro_ld][p0][0])[kk] = pa;
            reinterpret_cast<float4*>(&stage[buf ^ 1][ro_ld][p0 + 2][0])[kk] = pb;
        }
        __syncthreads();
    }
    // epilogue: horizontal for the last iteration's vertical output
    {
        const int vb = (nIter - 1) & 1;
        const int roBase = rin0 + 2 * (nIter - 1) - 10;
        do_horiz(vsb[vb], roBase, o0, o1, b, t, acc0, acc1, acc2);
    }

    // ---- block reduce over 192 threads ----
    red[0][t] = (t < 182) ? acc0 : 0.f;
    red[1][t] = (t < 182) ? acc1 : 0.f;
    red[2][t] = (t < 182) ? acc2 : 0.f;
    __syncthreads();
    // tree-ish reduce by 3 warps
    if (t < 96) {
        const int f = t / 32, lane = t % 32;
        float s = red[f][lane] + red[f][lane + 32] + red[f][lane + 64] +
                  red[f][lane + 96] + red[f][lane + 128] + red[f][lane + 160];
#pragma unroll
        for (int off = 16; off > 0; off >>= 1)
            s += __shfl_down_sync(0xffffffffu, s, off);
        if (lane == 0)
            g_part[(((size_t)band * BB + b) * FF + f) * CC + c] = s;
    }
}

// ---------------------------------------------------------------------------
// K3: sum band partials -> ssim_info; spatial gate conv + MLP + sigmoid.
// ---------------------------------------------------------------------------
__global__ void __launch_bounds__(512) k3_gate(const float* __restrict__ sw,
                                               const float* __restrict__ W1,
                                               const float* __restrict__ b1,
                                               const float* __restrict__ W2,
                                               const float* __restrict__ b2,
                                               float* __restrict__ out,
                                               int out_size) {
    __shared__ float si[BB][FF][CC];
    __shared__ float gg[BB][CC];
    __shared__ float h1[BB][CC];

    const int t = threadIdx.x;
    const int b = t >> 6, c = t & 63;

    for (int i = t; i < BB * FF * CC; i += 512) {
        float s = g_part[i] + g_part[BB * FF * CC + i] +
                  g_part[2 * BB * FF * CC + i] + g_part[3 * BB * FF * CC + i];
        (&si[0][0][0])[i] = s * INV_NPIX;
    }
    __syncthreads();

    float s = 0.f;
#pragma unroll
    for (int f = 0; f < 3; f++) {
#pragma unroll
        for (int kk = 0; kk < 3; kk++) {
            int cc = c + kk - 1;
            if (cc >= 0 && cc < CC) s = fmaf(sw[f * 3 + kk], si[b][f][cc], s);
        }
    }
    gg[b][c] = fmaxf(s, 0.f);
    __syncthreads();

    float a = b1[c];
#pragma unroll 8
    for (int j = 0; j < CC; j++) a = fmaf(gg[b][j], W1[c * CC + j], a);
    h1[b][c] = fmaxf(a, 0.f);
    __syncthreads();

    float o = b2[c];
#pragma unroll 8
    for (int j = 0; j < CC; j++) o = fmaf(h1[b][j], W2[c * CC + j], o);
    out[b * CC + c] = 1.f / (1.f + expf(-o));

    if (out_size >= BB * CC + BB * FF * CC) {
        for (int i = t; i < BB * FF * CC; i += 512)
            out[BB * CC + i] = (&si[0][0][0])[i];
    }
}

// ---------------------------------------------------------------------------
extern "C" void kernel_launch(void* const* d_in, const int* in_sizes, int n_in,
                              void* d_out, int out_size) {
    const float* x  = (const float*)d_in[0];
    const float* xf = (const float*)d_in[1];
    const float* sw = (const float*)d_in[2];
    const float* W1 = (const float*)d_in[3];
    const float* b1 = (const float*)d_in[4];
    const float* W2 = (const float*)d_in[5];
    const float* b2 = (const float*)d_in[6];
    float* out = (float*)d_out;

    k1_musig<<<dim3(BB * FF, 8), 192>>>(xf);
    k2_ssim<<<dim3(CC, BB, NBAND), 192>>>(x, xf);
    k3_gate<<<1, 512>>>(sw, W1, b1, W2, b2, out, out_size);
}

// round 3
// speedup vs baseline: 2.0192x; 1.1299x over previous
#include <cuda_runtime.h>
#include <cstdint>

// Problem constants
#define BB 8
#define CC 64
#define FF 3
#define HH 192
#define WW 192
#define HO 182
#define WO 182
#define C1S 0.01f   // (0.01*10)^2
#define C2S 0.09f   // (0.03*10)^2
#define INV_NPIX (1.0f/33124.0f)
#define NBAND 4
#define K1B 12

// mu_f/sig_f per (b,f) plane, packed {mu,sig}; +2 pad (horizontal float4 overread)
__device__ __align__(16) float2 g_musig[BB * FF * HO * WO + 2];
// per-band partial ssim sums [band][B][F][C]
__device__ float g_part[NBAND * BB * FF * CC];

// 11-tap gaussian (sigma=1.5); compile-time constants -> FFMA-imm
__device__ __forceinline__ float wt(int i) {
    switch (i) {
        case 0: case 10: return 0.00102838f;
        case 1: case 9:  return 0.00759876f;
        case 2: case 8:  return 0.03600077f;
        case 3: case 7:  return 0.10936069f;
        case 4: case 6:  return 0.21300553f;
        default:         return 0.26601173f;
    }
}

// Transposed-FIR push (10-reg state per FIR)
__device__ __forceinline__ float fir_push(float (&P)[10], float h) {
    float out = fmaf(wt(10), h, P[0]);
#pragma unroll
    for (int m = 0; m < 9; m++) P[m] = fmaf(wt(9 - m), h, P[m + 1]);
    P[9] = wt(0) * h;
    return out;
}

__device__ __forceinline__ uint32_t s2u(const void* p) {
    return (uint32_t)__cvta_generic_to_shared(p);
}
__device__ __forceinline__ void cp16(uint32_t dst, const void* src, bool pred) {
    int sz = pred ? 16 : 0;
    asm volatile("cp.async.ca.shared.global [%0], [%1], 16, %2;\n"
                 :: "r"(dst), "l"(src), "r"(sz));
}
#define CP_COMMIT() asm volatile("cp.async.commit_group;\n" ::: "memory")
#define CP_WAIT0()  asm volatile("cp.async.wait_group 0;\n" ::: "memory")

// ---------------------------------------------------------------------------
// K1: mu_f/sig_f planes. grid (24, 12 bands), 192 threads.
// 4 rows/iter; vertical FIR in regs -> vsb -> horizontal 4 cols/thread.
// ---------------------------------------------------------------------------
__global__ void __launch_bounds__(192) k1_musig(const float* __restrict__ xf) {
    const int bf = blockIdx.x;
    const int band = blockIdx.y;
    const int t = threadIdx.x;

    __shared__ float stage[2][4][WW];     // [buf][rowoff][col]
    __shared__ float vsb[2][4][196];      // [quantity][rowoff][col(+pad)]

    const int r0 = 16 * band;
    const int r1 = (band == K1B - 1) ? HO : 16 * (band + 1);
    const int NIT = 7;  // ceil((16+10)/4) with guards

    const float* plane = xf + (size_t)bf * HH * WW;

    const int lrw = t / 48, lkk = t % 48;     // loader mapping
    const int hrw = t / 46, hcg = t % 46;     // horizontal mapping (t<184)
    const int j0 = 4 * hcg;

    float Pf[10], Pff[10];
#pragma unroll
    for (int m = 0; m < 10; m++) { Pf[m] = 0.f; Pff[m] = 0.f; }

    // prologue: rows r0..r0+3 into stage[0]
    {
        int r = r0 + lrw;
        bool v = r < HH;
        int rc = v ? r : HH - 1;
        cp16(s2u(&stage[0][lrw][4 * lkk]), plane + (size_t)rc * WW + 4 * lkk, v);
        CP_COMMIT(); CP_WAIT0();
    }
    __syncthreads();

    for (int i = 0; i < NIT; ++i) {
        const int buf = i & 1;
        if (i + 1 < NIT) {
            int r = r0 + 4 * (i + 1) + lrw;
            bool v = r < HH;
            int rc = v ? r : HH - 1;
            cp16(s2u(&stage[buf ^ 1][lrw][4 * lkk]), plane + (size_t)rc * WW + 4 * lkk, v);
        }
        CP_COMMIT();
        // vertical
#pragma unroll
        for (int rw = 0; rw < 4; rw++) {
            float h = stage[buf][rw][t];
            vsb[0][rw][t] = fir_push(Pf, h);
            vsb[1][rw][t] = fir_push(Pff, h * h);
        }
        __syncthreads();
        // horizontal
        const int ro = r0 + 4 * i + hrw - 10;
        if (t < 184 && ro >= r0 && ro < r1) {
            float a[16], b[16];
#pragma unroll
            for (int ch = 0; ch < 4; ch++) {
                float4 u = *reinterpret_cast<const float4*>(&vsb[0][hrw][j0 + 4 * ch]);
                float4 v = *reinterpret_cast<const float4*>(&vsb[1][hrw][j0 + 4 * ch]);
                a[4*ch]=u.x; a[4*ch+1]=u.y; a[4*ch+2]=u.z; a[4*ch+3]=u.w;
                b[4*ch]=v.x; b[4*ch+1]=v.y; b[4*ch+2]=v.z; b[4*ch+3]=v.w;
            }
            float mu[4], s2[4];
#pragma unroll
            for (int cl = 0; cl < 4; cl++) {
                float sm = 0.f, ss = 0.f;
#pragma unroll
                for (int k = 0; k < 11; k++) {
                    sm = fmaf(wt(k), a[cl + k], sm);
                    ss = fmaf(wt(k), b[cl + k], ss);
                }
                mu[cl] = sm;
                s2[cl] = ss - sm * sm;
            }
            float2* orow = &g_musig[((size_t)bf * HO + ro) * WO + j0];
            float4 st0 = make_float4(mu[0], s2[0], mu[1], s2[1]);
            *reinterpret_cast<float4*>(orow) = st0;
            if (hcg < 45) {
                float4 st1 = make_float4(mu[2], s2[2], mu[3], s2[3]);
                *reinterpret_cast<float4*>(orow + 2) = st1;
            }
        }
        CP_WAIT0();
        __syncthreads();
    }
}

// ---------------------------------------------------------------------------
// K2: main SSIM kernel. grid (c=64, b=8, band=4), 192 threads.
// 4 rows/iter; 5 vertical FIRs in regs -> vsb -> horizontal 4 cols/thread.
// ---------------------------------------------------------------------------
__global__ void __launch_bounds__(192) k2_ssim(const float* __restrict__ x,
                                               const float* __restrict__ xf) {
    const int c = blockIdx.x;
    const int b = blockIdx.y;
    const int band = blockIdx.z;
    const int t = threadIdx.x;

    __shared__ float stage[2][4][4][WW];  // [buf][rowoff][plane][col]
    __shared__ float vsb[5][4][196];      // [quantity][rowoff][col(+pad)]
    __shared__ float red[3][192];

    const int obs[5] = {0, 46, 92, 138, 182};
    const int o0 = obs[band], o1 = obs[band + 1];
    const int rin0 = o0;
    const int NIT = 14;

    const float* xp = x + ((size_t)(b * CC + c)) * HH * WW;
    const float* fp = xf + (size_t)b * FF * HH * WW;
    const float* plsrc[4] = { xp, fp, fp + (size_t)HH * WW, fp + (size_t)2 * HH * WW };

    const int lrw = t / 48, lkk = t % 48;   // loader: plane l, row lrw, chunk lkk
    const int hrw = t / 46, hcg = t % 46;   // horizontal (t<184)
    const int j0 = 4 * hcg;

    float P[5][10];
#pragma unroll
    for (int q = 0; q < 5; q++)
#pragma unroll
        for (int m = 0; m < 10; m++) P[q][m] = 0.f;

    float acc0 = 0.f, acc1 = 0.f, acc2 = 0.f;

    // prologue: rows rin0..rin0+3 all 4 planes into stage[0]
    {
        int r = rin0 + lrw;
        bool v = r < HH;
        int rc = v ? r : HH - 1;
#pragma unroll
        for (int l = 0; l < 4; l++)
            cp16(s2u(&stage[0][lrw][l][4 * lkk]),
                 plsrc[l] + (size_t)rc * WW + 4 * lkk, v);
        CP_COMMIT(); CP_WAIT0();
    }
    __syncthreads();

    for (int i = 0; i < NIT; ++i) {
        const int buf = i & 1;
        // prefetch next 4 rows
        if (i + 1 < NIT) {
            int r = rin0 + 4 * (i + 1) + lrw;
            bool v = r < HH;
            int rc = v ? r : HH - 1;
#pragma unroll
            for (int l = 0; l < 4; l++)
                cp16(s2u(&stage[buf ^ 1][lrw][l][4 * lkk]),
                     plsrc[l] + (size_t)rc * WW + 4 * lkk, v);
        }
        CP_COMMIT();

        // ---- vertical FIRs, 4 rows ----
#pragma unroll
        for (int rw = 0; rw < 4; rw++) {
            float xv = stage[buf][rw][0][t];
            float f0 = stage[buf][rw][1][t];
            float f1 = stage[buf][rw][2][t];
            float f2 = stage[buf][rw][3][t];
            vsb[0][rw][t] = fir_push(P[0], xv);
            vsb[1][rw][t] = fir_push(P[1], xv * xv);
            vsb[2][rw][t] = fir_push(P[2], f0 * xv);
            vsb[3][rw][t] = fir_push(P[3], f1 * xv);
            vsb[4][rw][t] = fir_push(P[4], f2 * xv);
        }
        __syncthreads();

        // ---- horizontal + SSIM (each thread: 1 row, 4 cols) ----
        const int ro = rin0 + 4 * i + hrw - 10;
        if (t < 184 && ro >= o0 && ro < o1) {
            float Hq[5][4];
#pragma unroll
            for (int q = 0; q < 5; q++) {
                float v[16];
#pragma unroll
                for (int ch = 0; ch < 4; ch++) {
                    float4 u = *reinterpret_cast<const float4*>(&vsb[q][hrw][j0 + 4 * ch]);
                    v[4*ch]=u.x; v[4*ch+1]=u.y; v[4*ch+2]=u.z; v[4*ch+3]=u.w;
                }
#pragma unroll
                for (int cl = 0; cl < 4; cl++) {
                    float s = 0.f;
#pragma unroll
                    for (int k = 0; k < 11; k++) s = fmaf(wt(k), v[cl + k], s);
                    Hq[q][cl] = s;
                }
            }
            // mu_f/sig_f for 4 cols x 3 f: 6 LDG.128 (L2-resident)
            float muf_[3][4], sigf_[3][4];
#pragma unroll
            for (int f = 0; f < 3; f++) {
                const float4* mr = reinterpret_cast<const float4*>(
                    &g_musig[((size_t)(b * FF + f) * HO + ro) * WO + j0]);
                float4 m01 = mr[0], m23 = mr[1];
                muf_[f][0]=m01.x; sigf_[f][0]=m01.y;
                muf_[f][1]=m01.z; sigf_[f][1]=m01.w;
                muf_[f][2]=m23.x; sigf_[f][2]=m23.y;
                muf_[f][3]=m23.z; sigf_[f][3]=m23.w;
            }
#pragma unroll
            for (int cl = 0; cl < 4; cl++) {
                if (j0 + cl < WO) {
                    float mux  = Hq[0][cl];
                    float sigx = Hq[1][cl] - mux * mux;
                    float mx2c = fmaf(mux, mux, C1S);
                    float sxc  = sigx + C2S;
#pragma unroll
                    for (int f = 0; f < 3; f++) {
                        float muf  = muf_[f][cl];
                        float sigf = sigf_[f][cl];
                        float tp   = muf * mux;
                        float sfx  = Hq[2 + f][cl] - tp;
                        float v1   = fmaf(2.f, sfx, C2S);
                        float v2   = sigf + sxc;
                        float num  = fmaf(2.f, tp, C1S) * v1;
                        float den  = fmaf(muf, muf, mx2c) * v2;
                        float rr   = __fdividef(num, den);
                        if (f == 0) acc0 += rr; else if (f == 1) acc1 += rr; else acc2 += rr;
                    }
                }
            }
        }
        CP_WAIT0();
        __syncthreads();
    }

    // ---- block reduce over 184 active threads ----
    red[0][t] = (t < 184) ? acc0 : 0.f;
    red[1][t] = (t < 184) ? acc1 : 0.f;
    red[2][t] = (t < 184) ? acc2 : 0.f;
    __syncthreads();
    if (t < 96) {
        const int f = t / 32, lane = t % 32;
        float s = red[f][lane] + red[f][lane + 32] + red[f][lane + 64] +
                  red[f][lane + 96] + red[f][lane + 128] + red[f][lane + 160];
#pragma unroll
        for (int off = 16; off > 0; off >>= 1)
            s += __shfl_down_sync(0xffffffffu, s, off);
        if (lane == 0)
            g_part[(((size_t)band * BB + b) * FF + f) * CC + c] = s;
    }
}

// ---------------------------------------------------------------------------
// K3: sum band partials -> ssim_info; conv + MLP + sigmoid. 1 block, 512 thr.
// ---------------------------------------------------------------------------
__global__ void __launch_bounds__(512) k3_gate(const float* __restrict__ sw,
                                               const float* __restrict__ W1,
                                               const float* __restrict__ b1,
                                               const float* __restrict__ W2,
                                               const float* __restrict__ b2,
                                               float* __restrict__ out,
                                               int out_size) {
    __shared__ float si[BB][FF][CC];
    __shared__ float gg[BB][CC];
    __shared__ float h1[BB][CC];

    const int t = threadIdx.x;
    const int b = t >> 6, c = t & 63;

    for (int i = t; i < BB * FF * CC; i += 512) {
        float s = g_part[i] + g_part[BB * FF * CC + i] +
                  g_part[2 * BB * FF * CC + i] + g_part[3 * BB * FF * CC + i];
        (&si[0][0][0])[i] = s * INV_NPIX;
    }
    __syncthreads();

    float s = 0.f;
#pragma unroll
    for (int f = 0; f < 3; f++) {
#pragma unroll
        for (int kk = 0; kk < 3; kk++) {
            int cc = c + kk - 1;
            if (cc >= 0 && cc < CC) s = fmaf(sw[f * 3 + kk], si[b][f][cc], s);
        }
    }
    gg[b][c] = fmaxf(s, 0.f);
    __syncthreads();

    float a = b1[c];
#pragma unroll 8
    for (int j = 0; j < CC; j++) a = fmaf(gg[b][j], W1[c * CC + j], a);
    h1[b][c] = fmaxf(a, 0.f);
    __syncthreads();

    float o = b2[c];
#pragma unroll 8
    for (int j = 0; j < CC; j++) o = fmaf(h1[b][j], W2[c * CC + j], o);
    out[b * CC + c] = 1.f / (1.f + expf(-o));

    if (out_size >= BB * CC + BB * FF * CC) {
        for (int i = t; i < BB * FF * CC; i += 512)
            out[BB * CC + i] = (&si[0][0][0])[i];
    }
}

// ---------------------------------------------------------------------------
extern "C" void kernel_launch(void* const* d_in, const int* in_sizes, int n_in,
                              void* d_out, int out_size) {
    const float* x  = (const float*)d_in[0];
    const float* xf = (const float*)d_in[1];
    const float* sw = (const float*)d_in[2];
    const float* W1 = (const float*)d_in[3];
    const float* b1 = (const float*)d_in[4];
    const float* W2 = (const float*)d_in[5];
    const float* b2 = (const float*)d_in[6];
    float* out = (float*)d_out;

    k1_musig<<<dim3(BB * FF, K1B), 192>>>(xf);
    k2_ssim<<<dim3(CC, BB, NBAND), 192>>>(x, xf);
    k3_gate<<<1, 512>>>(sw, W1, b1, W2, b2, out, out_size);
}